// round 5
// baseline (speedup 1.0000x reference)
#include <cuda_runtime.h>
#include <math.h>
#include <stdint.h>

#define NTOK 2048
#define DIM  768
#define FF   3072
#define NE   8
#define NL   4
#define NA   (NTOK*2)

// fp32 smem tiles per stage: A[128][36], B[32][136]  (words)
#define AW 36
#define BW 136
#define OFF_B  4608              // words: 128*36
#define STAGE_WORDS 8960         // 4608 + 32*136
#define STAGE_BYTES (STAGE_WORDS*4)
#define SMEM_DYN (2*STAGE_BYTES)

// ---------------- scratch (static device globals; no allocation) -------------
__device__ float g_h   [NTOK*DIM];
__device__ float g_xln [NTOK*DIM];
__device__ float g_tmp [NTOK*DIM];
__device__ float g_H1  [(size_t)NA*FF];
__device__ float g_Y   [NA*DIM];
__device__ int   g_counts[NL*NE];
__device__ int   g_cursor[NL*NE];
__device__ int   g_off   [NL*(NE+1)];
__device__ int   g_tok [NA];
__device__ int   g_pair[NA];
__device__ float g_gw  [NA];
__device__ int   g_re  [NTOK*2];
__device__ float g_rw  [NTOK*2];

// ---------------- helpers ----------------------------------------------------
__device__ __forceinline__ uint32_t smem_u32(const void* p) {
    uint32_t a;
    asm("{ .reg .u64 t; cvta.to.shared.u64 t, %1; cvt.u32.u64 %0, t; }" : "=r"(a) : "l"(p));
    return a;
}
__device__ __forceinline__ void tf32split(float v, uint32_t& hi, uint32_t& lo) {
    uint32_t h;
    asm("cvt.rna.tf32.f32 %0, %1;" : "=r"(h) : "f"(v));
    float r = v - __uint_as_float(h);
    uint32_t l;
    asm("cvt.rna.tf32.f32 %0, %1;" : "=r"(l) : "f"(r));
    hi = h; lo = l;
}

#define MMAT(acc, a, b0v, b1v) \
    asm volatile("mma.sync.aligned.m16n8k8.row.col.f32.tf32.tf32.f32 " \
        "{%0,%1,%2,%3},{%4,%5,%6,%7},{%8,%9},{%0,%1,%2,%3};" \
        : "+f"((acc)[0]), "+f"((acc)[1]), "+f"((acc)[2]), "+f"((acc)[3]) \
        : "r"((a)[0]), "r"((a)[1]), "r"((a)[2]), "r"((a)[3]), "r"(b0v), "r"(b1v))

#define CPA(dst, src)   asm volatile("cp.async.cg.shared.global [%0], [%1], 16;" :: "r"(dst), "l"(src))
#define CPA_Z(dst, src) asm volatile("cp.async.cg.shared.global [%0], [%1], 16, 0;" :: "r"(dst), "l"(src))
#define CPC()  asm volatile("cp.async.commit_group;" ::: "memory")
#define CPW0() asm volatile("cp.async.wait_group 0;" ::: "memory")
#define CPW1() asm volatile("cp.async.wait_group 1;" ::: "memory")

__device__ __forceinline__ float warpSum(float v) {
    #pragma unroll
    for (int o = 16; o > 0; o >>= 1) v += __shfl_xor_sync(0xffffffffu, v, o);
    return v;
}

__global__ void zero_k() {
    int i = threadIdx.x;
    if (i < NL*NE) { g_counts[i] = 0; g_cursor[i] = 0; }
}

// ---------------- LayerNorm (+ optional gate / top-2 routing) ---------------
__global__ void ln_gate(const float* __restrict__ in, float* __restrict__ out,
                        const float* __restrict__ gam, const float* __restrict__ bet,
                        const float* __restrict__ wg, int layer)
{
    __shared__ float s[DIM];
    __shared__ float red[8];
    __shared__ float sstat;
    __shared__ float logits[NE];

    const int t = blockIdx.x, tid = threadIdx.x;
    const int lane = tid & 31, wid = tid >> 5;
    const float* row = in + (size_t)t*DIM;

    float lsum = 0.f;
    for (int d = tid; d < DIM; d += 256) { float v = row[d]; s[d] = v; lsum += v; }
    lsum = warpSum(lsum);
    if (lane == 0) red[wid] = lsum;
    __syncthreads();
    if (tid == 0) { float z = 0.f; for (int i = 0; i < 8; i++) z += red[i]; sstat = z / DIM; }
    __syncthreads();
    const float mu = sstat;

    float lvar = 0.f;
    for (int d = tid; d < DIM; d += 256) { float dv = s[d] - mu; lvar += dv*dv; }
    lvar = warpSum(lvar);
    __syncthreads();
    if (lane == 0) red[wid] = lvar;
    __syncthreads();
    if (tid == 0) { float z = 0.f; for (int i = 0; i < 8; i++) z += red[i]; sstat = rsqrtf(z / DIM + 1e-5f); }
    __syncthreads();
    const float rstd = sstat;

    for (int d = tid; d < DIM; d += 256) {
        float o = (s[d] - mu) * rstd * gam[d] + bet[d];
        out[(size_t)t*DIM + d] = o;
        s[d] = o;
    }
    if (!wg) return;
    __syncthreads();

    float acc = 0.f;
    for (int d = lane; d < DIM; d += 32) acc += s[d] * wg[d*NE + wid];
    acc = warpSum(acc);
    if (lane == 0) logits[wid] = acc;
    __syncthreads();

    if (tid == 0) {
        float v0 = -1e30f; int e0 = 0;
        #pragma unroll
        for (int e = 0; e < NE; e++) if (logits[e] > v0) { v0 = logits[e]; e0 = e; }
        float v1 = -1e30f; int e1 = 0;
        #pragma unroll
        for (int e = 0; e < NE; e++) if (e != e0 && logits[e] > v1) { v1 = logits[e]; e1 = e; }
        float ex  = expf(v1 - v0);
        float inv = 1.f / (1.f + ex);
        g_re[2*t] = e0;  g_re[2*t+1] = e1;
        g_rw[2*t] = inv; g_rw[2*t+1] = ex * inv;
        atomicAdd(&g_counts[layer*NE + e0], 1);
        atomicAdd(&g_counts[layer*NE + e1], 1);
    }
}

__global__ void scan_k(int layer) {
    if (threadIdx.x == 0) {
        int s = 0;
        for (int e = 0; e < NE; e++) { g_off[layer*(NE+1) + e] = s; s += g_counts[layer*NE + e]; }
        g_off[layer*(NE+1) + NE] = s;
    }
}

__global__ void scatter_k(int layer) {
    int t = blockIdx.x * blockDim.x + threadIdx.x;
    if (t >= NTOK) return;
    #pragma unroll
    for (int k = 0; k < 2; k++) {
        int e = g_re[2*t + k];
        int p = atomicAdd(&g_cursor[layer*NE + e], 1);
        int i = g_off[layer*(NE+1) + e] + p;
        g_tok[i]  = t;
        g_pair[i] = 2*t + k;
        g_gw[i]   = g_rw[2*t + k];
    }
}

__global__ void combine_k() {
    int idx = blockIdx.x * 256 + threadIdx.x;
    int t = idx / DIM, d = idx - t*DIM;
    float v = g_h[idx];
    v = v + g_Y[(size_t)(2*t)*DIM + d];
    v = v + g_Y[(size_t)(2*t + 1)*DIM + d];
    g_h[idx] = v;
}

// ---------------- 3xTF32 GEMM: cp.async double-buffered, reg-side split ------
// C = A[M,K] * B[K,N] + bias;  A row-major, B row-major [K,N].
// mode 0: plain  (out = outF rows contiguous)
// mode 1: A rows via g_tok; out = relu -> g_H1
// mode 2: A = g_H1 rows at base+lm; out = gw * (.) -> g_Y rows g_pair
__global__ void __launch_bounds__(256, 2)
tf_gemm(int mode, int layer,
        const float* __restrict__ A, const float* __restrict__ Bsrc,
        const float* __restrict__ bias, float* __restrict__ outF,
        int M, int Nn, int Kd)
{
    extern __shared__ float sm[];
    const int tid = threadIdx.x;
    const int lane = tid & 31, wid = tid >> 5;
    const int warpM = wid >> 2, warpN = wid & 3;
    const int g = lane >> 2, tg = lane & 3;
    const int n0 = blockIdx.x*128, m0 = blockIdx.y*128;

    int Mloc = M, base = 0;
    if (mode == 1 || mode == 2) {
        int e = blockIdx.z;
        Mloc = g_counts[layer*NE + e];
        if (m0 >= Mloc) return;
        base = g_off[layer*(NE+1) + e];
        Bsrc += (size_t)(layer*NE + e) * FF * DIM;
        bias += (size_t)(layer*NE + e) * ((mode == 1) ? FF : DIM);
    } else {
        if (m0 >= M) return;
    }

    const uint32_t sbase = smem_u32(sm);

    // A loader: thread -> row (tid>>1), half (tid&1); 4x 16B chunks
    const int ldrowA = tid >> 1, halfA = tid & 1;
    const float* pA = nullptr;
    {
        int lm = m0 + ldrowA;
        if (lm < Mloc) {
            int idx;
            if (mode == 1)      idx = g_tok[base + lm];
            else if (mode == 2) idx = base + lm;
            else                idx = lm;
            pA = A + (size_t)idx*Kd;
        }
    }
    // B loader: thread -> k-row (tid>>3), col group (tid&7); 4x 16B chunks
    const int ldrowB = tid >> 3, colB = tid & 7;
    const float* pB = Bsrc + (size_t)ldrowB*Nn + n0;

    const uint32_t aDst0 = sbase + (uint32_t)(ldrowA*AW + halfA*16)*4u;
    const uint32_t bDst0 = sbase + (uint32_t)(OFF_B + ldrowB*BW)*4u;

    float acc[4][4][4];
    #pragma unroll
    for (int a = 0; a < 4; a++)
        #pragma unroll
        for (int b = 0; b < 4; b++)
            #pragma unroll
            for (int c = 0; c < 4; c++) acc[a][b][c] = 0.f;

    const int nch = Kd >> 5;

    // ---- stage load issue ----
    #define ISSUE(stage, kt) do {                                              \
        uint32_t aD = aDst0 + (uint32_t)(stage)*STAGE_BYTES;                   \
        uint32_t bD = bDst0 + (uint32_t)(stage)*STAGE_BYTES;                   \
        _Pragma("unroll")                                                      \
        for (int q = 0; q < 4; q++) {                                          \
            if (pA) { CPA(aD + q*16u, pA + (kt) + halfA*16 + q*4); }           \
            else    { CPA_Z(aD + q*16u, Bsrc); }                               \
            CPA(bD + (uint32_t)((colB + 8*q)*16), pB + (size_t)(kt)*Nn + (colB + 8*q)*4); \
        }                                                                      \
    } while (0)

    ISSUE(0, 0);
    CPC();

    for (int ch = 0; ch < nch; ch++) {
        const int cur = ch & 1;
        if (ch + 1 < nch) { ISSUE((ch + 1) & 1, (ch + 1)*32); CPC(); CPW1(); }
        else              { CPW0(); }
        __syncthreads();

        const float* sA = sm + (size_t)cur*STAGE_WORDS;
        const float* sB = sA + OFF_B;

        #pragma unroll
        for (int ks = 0; ks < 4; ks++) {
            const int k0 = ks*8;
            uint32_t bh0[4], bh1[4], bl0[4], bl1[4];
            #pragma unroll
            for (int nt = 0; nt < 4; nt++) {
                int n = warpN*32 + nt*8 + g;
                tf32split(sB[(k0+tg)*BW + n],   bh0[nt], bl0[nt]);
                tf32split(sB[(k0+tg+4)*BW + n], bh1[nt], bl1[nt]);
            }
            #pragma unroll
            for (int mt = 0; mt < 4; mt++) {
                int rowa = warpM*64 + mt*16 + g;
                int c = k0 + tg;
                uint32_t ah[4], al[4];
                tf32split(sA[rowa*AW + c],       ah[0], al[0]);
                tf32split(sA[(rowa+8)*AW + c],   ah[1], al[1]);
                tf32split(sA[rowa*AW + c + 4],   ah[2], al[2]);
                tf32split(sA[(rowa+8)*AW + c+4], ah[3], al[3]);
                #pragma unroll
                for (int nt = 0; nt < 4; nt++) {
                    MMAT(acc[mt][nt], ah, bh0[nt], bh1[nt]);
                    MMAT(acc[mt][nt], ah, bl0[nt], bl1[nt]);
                    MMAT(acc[mt][nt], al, bh0[nt], bh1[nt]);
                }
            }
        }
        __syncthreads();
    }
    #undef ISSUE

    // ---------------- epilogue ----------------
    #pragma unroll
    for (int mt = 0; mt < 4; mt++) {
        #pragma unroll
        for (int half_m = 0; half_m < 2; half_m++) {
            const int mrow = m0 + warpM*64 + mt*16 + g + half_m*8;
            if (mrow >= Mloc) continue;
            float gww = 1.f;
            size_t rowoff;
            if (mode == 1) {
                rowoff = (size_t)(base + mrow) * FF;
            } else if (mode == 2) {
                int gi = base + mrow;
                gww = g_gw[gi];
                rowoff = (size_t)g_pair[gi] * DIM;
            } else {
                rowoff = (size_t)mrow * Nn;
            }
            #pragma unroll
            for (int nt = 0; nt < 4; nt++) {
                const int col = n0 + warpN*32 + nt*8 + tg*2;
                float2 bs = *(const float2*)(bias + col);
                float v0 = acc[mt][nt][2*half_m]     + bs.x;
                float v1 = acc[mt][nt][2*half_m + 1] + bs.y;
                if (mode == 1) {
                    v0 = fmaxf(v0, 0.f); v1 = fmaxf(v1, 0.f);
                    *(float2*)(g_H1 + rowoff + col) = make_float2(v0, v1);
                } else if (mode == 2) {
                    *(float2*)(g_Y + rowoff + col) = make_float2(gww*v0, gww*v1);
                } else {
                    *(float2*)(outF + rowoff + col) = make_float2(v0, v1);
                }
            }
        }
    }
}

// ---------------- host -------------------------------------------------------
extern "C" void kernel_launch(void* const* d_in, const int* in_sizes, int n_in,
                              void* d_out, int out_size)
{
    (void)in_sizes; (void)n_in; (void)out_size;
    const float* x      = (const float*)d_in[0];
    const float* w_in   = (const float*)d_in[1];
    const float* b_in   = (const float*)d_in[2];
    const float* gi     = (const float*)d_in[3];
    const float* bi     = (const float*)d_in[4];
    const float* g_lnp  = (const float*)d_in[5];
    const float* be_lnp = (const float*)d_in[6];
    const float* wgp    = (const float*)d_in[7];
    const float* w1p    = (const float*)d_in[8];
    const float* b1p    = (const float*)d_in[9];
    const float* w2p    = (const float*)d_in[10];
    const float* b2p    = (const float*)d_in[11];
    const float* w_out  = (const float*)d_in[12];
    const float* b_out  = (const float*)d_in[13];
    const float* g_o    = (const float*)d_in[14];
    const float* be_o   = (const float*)d_in[15];

    float *hP, *tmpP, *xlnP, *h1P;
    cudaGetSymbolAddress((void**)&hP,   g_h);
    cudaGetSymbolAddress((void**)&tmpP, g_tmp);
    cudaGetSymbolAddress((void**)&xlnP, g_xln);
    cudaGetSymbolAddress((void**)&h1P,  g_H1);

    cudaFuncSetAttribute(tf_gemm, cudaFuncAttributeMaxDynamicSharedMemorySize, SMEM_DYN);

    zero_k<<<1, 64>>>();

    // input projection + LN -> residual h
    tf_gemm<<<dim3(DIM/128, NTOK/128), 256, SMEM_DYN>>>(
        0, 0, x, w_in, b_in, tmpP, NTOK, DIM, DIM);
    ln_gate<<<NTOK, 256>>>(tmpP, hP, gi, bi, nullptr, 0);

    for (int l = 0; l < NL; l++) {
        ln_gate<<<NTOK, 256>>>(hP, xlnP, g_lnp + (size_t)l*DIM, be_lnp + (size_t)l*DIM,
                               wgp + (size_t)l*DIM*NE, l);
        scan_k<<<1, 32>>>(l);
        scatter_k<<<NTOK/256, 256>>>(l);
        tf_gemm<<<dim3(FF/128, NTOK/128, NE), 256, SMEM_DYN>>>(
            1, l, xlnP, w1p, b1p, nullptr, 0, FF, DIM);
        tf_gemm<<<dim3(DIM/128, NTOK/128, NE), 256, SMEM_DYN>>>(
            2, l, h1P, w2p, b2p, nullptr, 0, DIM, FF);
        combine_k<<<NTOK*DIM/256, 256>>>();
    }

    // output projection + LN -> d_out
    tf_gemm<<<dim3(DIM/128, NTOK/128), 256, SMEM_DYN>>>(
        0, 0, hP, w_out, b_out, tmpP, NTOK, DIM, DIM);
    ln_gate<<<NTOK, 256>>>(tmpP, (float*)d_out, g_o, be_o, nullptr, 0);
}

// round 6
// speedup vs baseline: 1.5330x; 1.5330x over previous
#include <cuda_runtime.h>
#include <cuda_fp16.h>
#include <math.h>
#include <stdint.h>

#define NTOK 2048
#define DIM  768
#define FF   3072
#define NE   8
#define NL   4
#define NA   (NTOK*2)

// smem (halves): sAh[128*40], sAl, sBh[128*40], sBl   (row stride 40 halves)
#define AWH 40
#define SMEM_DYN (4*128*40*2)

// ---------------- scratch (static device globals; no allocation) -------------
__device__ float g_h   [NTOK*DIM];
__device__ float g_xln [NTOK*DIM];
__device__ float g_tmp [NTOK*DIM];
__device__ float g_H1  [(size_t)NA*FF];
__device__ float g_Y   [NA*DIM];
__device__ int   g_counts[NL*NE];
__device__ int   g_cursor[NL*NE];
__device__ int   g_off   [NL*(NE+1)];
__device__ int   g_tok [NA];
__device__ int   g_pair[NA];
__device__ float g_gw  [NA];
__device__ int   g_re  [NTOK*2];
__device__ float g_rw  [NTOK*2];

// ---------------- helpers ----------------------------------------------------
__device__ __forceinline__ void h2split(float a, float b, uint32_t& hi, uint32_t& lo) {
    __half ha = __float2half_rn(a), hb = __float2half_rn(b);
    float ra = a - __half2float(ha);
    float rb = b - __half2float(hb);
    __half la = __float2half_rn(ra), lb = __float2half_rn(rb);
    hi = (uint32_t)__half_as_ushort(ha) | ((uint32_t)__half_as_ushort(hb) << 16);
    lo = (uint32_t)__half_as_ushort(la) | ((uint32_t)__half_as_ushort(lb) << 16);
}

#define MMAH(acc, a, b0v, b1v) \
    asm volatile("mma.sync.aligned.m16n8k16.row.col.f32.f16.f16.f32 " \
        "{%0,%1,%2,%3},{%4,%5,%6,%7},{%8,%9},{%0,%1,%2,%3};" \
        : "+f"((acc)[0]), "+f"((acc)[1]), "+f"((acc)[2]), "+f"((acc)[3]) \
        : "r"((a)[0]), "r"((a)[1]), "r"((a)[2]), "r"((a)[3]), "r"(b0v), "r"(b1v))

__device__ __forceinline__ float warpSum(float v) {
    #pragma unroll
    for (int o = 16; o > 0; o >>= 1) v += __shfl_xor_sync(0xffffffffu, v, o);
    return v;
}

__global__ void zero_k() {
    int i = threadIdx.x;
    if (i < NL*NE) { g_counts[i] = 0; g_cursor[i] = 0; }
}

// ---------------- LayerNorm (+ optional gate / top-2 routing) ---------------
__global__ void ln_gate(const float* __restrict__ in, float* __restrict__ out,
                        const float* __restrict__ gam, const float* __restrict__ bet,
                        const float* __restrict__ wg, int layer)
{
    __shared__ float s[DIM];
    __shared__ float red[8];
    __shared__ float sstat;
    __shared__ float logits[NE];

    const int t = blockIdx.x, tid = threadIdx.x;
    const int lane = tid & 31, wid = tid >> 5;
    const float* row = in + (size_t)t*DIM;

    float lsum = 0.f;
    for (int d = tid; d < DIM; d += 256) { float v = row[d]; s[d] = v; lsum += v; }
    lsum = warpSum(lsum);
    if (lane == 0) red[wid] = lsum;
    __syncthreads();
    if (tid == 0) { float z = 0.f; for (int i = 0; i < 8; i++) z += red[i]; sstat = z / DIM; }
    __syncthreads();
    const float mu = sstat;

    float lvar = 0.f;
    for (int d = tid; d < DIM; d += 256) { float dv = s[d] - mu; lvar += dv*dv; }
    lvar = warpSum(lvar);
    __syncthreads();
    if (lane == 0) red[wid] = lvar;
    __syncthreads();
    if (tid == 0) { float z = 0.f; for (int i = 0; i < 8; i++) z += red[i]; sstat = rsqrtf(z / DIM + 1e-5f); }
    __syncthreads();
    const float rstd = sstat;

    for (int d = tid; d < DIM; d += 256) {
        float o = (s[d] - mu) * rstd * gam[d] + bet[d];
        out[(size_t)t*DIM + d] = o;
        s[d] = o;
    }
    if (!wg) return;
    __syncthreads();

    float acc = 0.f;
    for (int d = lane; d < DIM; d += 32) acc += s[d] * wg[d*NE + wid];
    acc = warpSum(acc);
    if (lane == 0) logits[wid] = acc;
    __syncthreads();

    if (tid == 0) {
        float v0 = -1e30f; int e0 = 0;
        #pragma unroll
        for (int e = 0; e < NE; e++) if (logits[e] > v0) { v0 = logits[e]; e0 = e; }
        float v1 = -1e30f; int e1 = 0;
        #pragma unroll
        for (int e = 0; e < NE; e++) if (e != e0 && logits[e] > v1) { v1 = logits[e]; e1 = e; }
        float ex  = expf(v1 - v0);
        float inv = 1.f / (1.f + ex);
        g_re[2*t] = e0;  g_re[2*t+1] = e1;
        g_rw[2*t] = inv; g_rw[2*t+1] = ex * inv;
        atomicAdd(&g_counts[layer*NE + e0], 1);
        atomicAdd(&g_counts[layer*NE + e1], 1);
    }
}

__global__ void scan_k(int layer) {
    if (threadIdx.x == 0) {
        int s = 0;
        for (int e = 0; e < NE; e++) { g_off[layer*(NE+1) + e] = s; s += g_counts[layer*NE + e]; }
        g_off[layer*(NE+1) + NE] = s;
    }
}

__global__ void scatter_k(int layer) {
    int t = blockIdx.x * blockDim.x + threadIdx.x;
    if (t >= NTOK) return;
    #pragma unroll
    for (int k = 0; k < 2; k++) {
        int e = g_re[2*t + k];
        int p = atomicAdd(&g_cursor[layer*NE + e], 1);
        int i = g_off[layer*(NE+1) + e] + p;
        g_tok[i]  = t;
        g_pair[i] = 2*t + k;
        g_gw[i]   = g_rw[2*t + k];
    }
}

__global__ void combine_k() {
    int idx = blockIdx.x * 256 + threadIdx.x;
    int t = idx / DIM, d = idx - t*DIM;
    float v = g_h[idx];
    v = v + g_Y[(size_t)(2*t)*DIM + d];
    v = v + g_Y[(size_t)(2*t + 1)*DIM + d];
    g_h[idx] = v;
}

// ---------------- 3x-fp16-split GEMM (m16n8k16, 128x128 tile, KC=32) --------
// C = A[M,K] * B[K,N] + bias;  A row-major fp32, B row-major [K,N] fp32.
// mode 0: plain  (out rows contiguous)
// mode 1: A rows via g_tok; out = relu -> g_H1
// mode 2: A = g_H1 rows at base+lm; out = gw * (.) -> g_Y rows g_pair
__global__ void __launch_bounds__(256, 2)
hm_gemm(int mode, int layer,
        const float* __restrict__ A, const float* __restrict__ Bsrc,
        const float* __restrict__ bias, float* __restrict__ outF,
        int M, int Nn, int Kd)
{
    extern __shared__ __half smh[];
    __half* sAh = smh;
    __half* sAl = smh + 5120;
    __half* sBh = smh + 10240;   // layout [n][k]: n row stride AWH halves
    __half* sBl = smh + 15360;

    const int tid = threadIdx.x;
    const int lane = tid & 31, wid = tid >> 5;
    const int warpM = wid >> 2, warpN = wid & 3;
    const int g = lane >> 2, tg = lane & 3;
    const int n0 = blockIdx.x*128, m0 = blockIdx.y*128;

    int Mloc = M, base = 0;
    if (mode == 1 || mode == 2) {
        int e = blockIdx.z;
        Mloc = g_counts[layer*NE + e];
        if (m0 >= Mloc) return;
        base = g_off[layer*(NE+1) + e];
        Bsrc += (size_t)(layer*NE + e) * FF * DIM;
        bias += (size_t)(layer*NE + e) * ((mode == 1) ? FF : DIM);
    } else {
        if (m0 >= M) return;
    }

    // A loader: thread -> row (tid>>1), k-half (tid&1) (16 floats = 4 float4)
    const int rowA = tid >> 1, halfA = tid & 1;
    const float* pA = nullptr;
    {
        int lm = m0 + rowA;
        if (lm < Mloc) {
            int idx;
            if (mode == 1)      idx = g_tok[base + lm];
            else if (mode == 2) idx = base + lm;
            else                idx = lm;
            pA = A + (size_t)idx*Kd + halfA*16;
        }
    }
    // B loader: thread -> n (tid&127), k-seg (tid>>7) of 16
    const int nB = tid & 127, segB = tid >> 7;
    const float* pB = Bsrc + n0 + nB + (size_t)segB*16*Nn;

    float acc[4][4][4];
    #pragma unroll
    for (int a = 0; a < 4; a++)
        #pragma unroll
        for (int b = 0; b < 4; b++)
            #pragma unroll
            for (int c = 0; c < 4; c++) acc[a][b][c] = 0.f;

    for (int kt = 0; kt < Kd; kt += 32) {
        __syncthreads();   // previous-iteration readers done
        // ---- A tile [128 rows x 32 k] -> split halves ----
        {
            int sa = rowA*AWH + halfA*16;
            #pragma unroll
            for (int q = 0; q < 4; q++) {
                float4 v = make_float4(0.f,0.f,0.f,0.f);
                if (pA) v = *(const float4*)(pA + kt + q*4);
                uint32_t h0,l0,h1,l1;
                h2split(v.x, v.y, h0, l0);
                h2split(v.z, v.w, h1, l1);
                *(uint32_t*)(sAh + sa + q*4)     = h0;
                *(uint32_t*)(sAh + sa + q*4 + 2) = h1;
                *(uint32_t*)(sAl + sa + q*4)     = l0;
                *(uint32_t*)(sAl + sa + q*4 + 2) = l1;
            }
        }
        // ---- B tile [32 k x 128 n] -> transposed split halves sB[n][k] ----
        {
            float bv[16];
            #pragma unroll
            for (int kk = 0; kk < 16; kk++)
                bv[kk] = pB[(size_t)(kt + kk)*Nn];
            int sb = nB*AWH + segB*16;
            #pragma unroll
            for (int w = 0; w < 8; w++) {
                uint32_t h, l;
                h2split(bv[2*w], bv[2*w+1], h, l);
                *(uint32_t*)(sBh + sb + 2*w) = h;
                *(uint32_t*)(sBl + sb + 2*w) = l;
            }
        }
        __syncthreads();

        // ---- 2 k16-steps ----
        #pragma unroll
        for (int ks = 0; ks < 2; ks++) {
            const int k0 = ks*16;
            uint32_t bh0[4], bh1[4], bl0[4], bl1[4];
            #pragma unroll
            for (int nt = 0; nt < 4; nt++) {
                int n = warpN*32 + nt*8 + g;
                bh0[nt] = *(const uint32_t*)(sBh + n*AWH + k0 + 2*tg);
                bh1[nt] = *(const uint32_t*)(sBh + n*AWH + k0 + 8 + 2*tg);
                bl0[nt] = *(const uint32_t*)(sBl + n*AWH + k0 + 2*tg);
                bl1[nt] = *(const uint32_t*)(sBl + n*AWH + k0 + 8 + 2*tg);
            }
            #pragma unroll
            for (int mt = 0; mt < 4; mt++) {
                int ra = warpM*64 + mt*16 + g;
                uint32_t ah[4], al[4];
                ah[0] = *(const uint32_t*)(sAh + ra*AWH     + k0 + 2*tg);
                ah[1] = *(const uint32_t*)(sAh + (ra+8)*AWH + k0 + 2*tg);
                ah[2] = *(const uint32_t*)(sAh + ra*AWH     + k0 + 8 + 2*tg);
                ah[3] = *(const uint32_t*)(sAh + (ra+8)*AWH + k0 + 8 + 2*tg);
                al[0] = *(const uint32_t*)(sAl + ra*AWH     + k0 + 2*tg);
                al[1] = *(const uint32_t*)(sAl + (ra+8)*AWH + k0 + 2*tg);
                al[2] = *(const uint32_t*)(sAl + ra*AWH     + k0 + 8 + 2*tg);
                al[3] = *(const uint32_t*)(sAl + (ra+8)*AWH + k0 + 8 + 2*tg);
                #pragma unroll
                for (int nt = 0; nt < 4; nt++) {
                    MMAH(acc[mt][nt], ah, bh0[nt], bh1[nt]);
                    MMAH(acc[mt][nt], ah, bl0[nt], bl1[nt]);
                    MMAH(acc[mt][nt], al, bh0[nt], bh1[nt]);
                }
            }
        }
    }

    // ---------------- epilogue ----------------
    #pragma unroll
    for (int mt = 0; mt < 4; mt++) {
        #pragma unroll
        for (int half_m = 0; half_m < 2; half_m++) {
            const int mrow = m0 + warpM*64 + mt*16 + g + half_m*8;
            if (mrow >= Mloc) continue;
            float gww = 1.f;
            size_t rowoff;
            if (mode == 1) {
                rowoff = (size_t)(base + mrow) * FF;
            } else if (mode == 2) {
                int gi = base + mrow;
                gww = g_gw[gi];
                rowoff = (size_t)g_pair[gi] * DIM;
            } else {
                rowoff = (size_t)mrow * Nn;
            }
            #pragma unroll
            for (int nt = 0; nt < 4; nt++) {
                const int col = n0 + warpN*32 + nt*8 + tg*2;
                float2 bs = *(const float2*)(bias + col);
                float v0 = acc[mt][nt][2*half_m]     + bs.x;
                float v1 = acc[mt][nt][2*half_m + 1] + bs.y;
                if (mode == 1) {
                    v0 = fmaxf(v0, 0.f); v1 = fmaxf(v1, 0.f);
                    *(float2*)(g_H1 + rowoff + col) = make_float2(v0, v1);
                } else if (mode == 2) {
                    *(float2*)(g_Y + rowoff + col) = make_float2(gww*v0, gww*v1);
                } else {
                    *(float2*)(outF + rowoff + col) = make_float2(v0, v1);
                }
            }
        }
    }
}

// ---------------- host -------------------------------------------------------
extern "C" void kernel_launch(void* const* d_in, const int* in_sizes, int n_in,
                              void* d_out, int out_size)
{
    (void)in_sizes; (void)n_in; (void)out_size;
    const float* x      = (const float*)d_in[0];
    const float* w_in   = (const float*)d_in[1];
    const float* b_in   = (const float*)d_in[2];
    const float* gi     = (const float*)d_in[3];
    const float* bi     = (const float*)d_in[4];
    const float* g_lnp  = (const float*)d_in[5];
    const float* be_lnp = (const float*)d_in[6];
    const float* wgp    = (const float*)d_in[7];
    const float* w1p    = (const float*)d_in[8];
    const float* b1p    = (const float*)d_in[9];
    const float* w2p    = (const float*)d_in[10];
    const float* b2p    = (const float*)d_in[11];
    const float* w_out  = (const float*)d_in[12];
    const float* b_out  = (const float*)d_in[13];
    const float* g_o    = (const float*)d_in[14];
    const float* be_o   = (const float*)d_in[15];

    float *hP, *tmpP, *xlnP, *h1P;
    cudaGetSymbolAddress((void**)&hP,   g_h);
    cudaGetSymbolAddress((void**)&tmpP, g_tmp);
    cudaGetSymbolAddress((void**)&xlnP, g_xln);
    cudaGetSymbolAddress((void**)&h1P,  g_H1);

    cudaFuncSetAttribute(hm_gemm, cudaFuncAttributeMaxDynamicSharedMemorySize, SMEM_DYN);

    zero_k<<<1, 64>>>();

    // input projection + LN -> residual h
    hm_gemm<<<dim3(DIM/128, NTOK/128), 256, SMEM_DYN>>>(
        0, 0, x, w_in, b_in, tmpP, NTOK, DIM, DIM);
    ln_gate<<<NTOK, 256>>>(tmpP, hP, gi, bi, nullptr, 0);

    for (int l = 0; l < NL; l++) {
        ln_gate<<<NTOK, 256>>>(hP, xlnP, g_lnp + (size_t)l*DIM, be_lnp + (size_t)l*DIM,
                               wgp + (size_t)l*DIM*NE, l);
        scan_k<<<1, 32>>>(l);
        scatter_k<<<NTOK/256, 256>>>(l);
        hm_gemm<<<dim3(FF/128, NTOK/128, NE), 256, SMEM_DYN>>>(
            1, l, xlnP, w1p, b1p, nullptr, 0, FF, DIM);
        hm_gemm<<<dim3(DIM/128, NTOK/128, NE), 256, SMEM_DYN>>>(
            2, l, h1P, w2p, b2p, nullptr, 0, DIM, FF);
        combine_k<<<NTOK*DIM/256, 256>>>();
    }

    // output projection + LN -> d_out
    hm_gemm<<<dim3(DIM/128, NTOK/128), 256, SMEM_DYN>>>(
        0, 0, hP, w_out, b_out, tmpP, NTOK, DIM, DIM);
    ln_gate<<<NTOK, 256>>>(tmpP, (float*)d_out, g_o, be_o, nullptr, 0);
}